// round 5
// baseline (speedup 1.0000x reference)
#include <cuda_runtime.h>
#include <cstdint>

// GenODE: z' = tanh(z W1^T + b1) W2^T + b2, N=8192 rows, D=64, H=128.
// Fixed-step RK4, dt = 1/63, one step per output interval.
//
// R5 = R3's occupancy (256 thr/CTA, 2 warps/SMSP, 1 row per thread-quad)
//    + R4's fma.rn.f32x2 packing along the output dimension.
// Rationale: FMA2 work per SM is config-invariant (4096 instr/SMSP/eval,
// rt=2 -> 8192 cyc floor). R4's 1 warp/SMSP left issue at 45% (latency
// exposed); the second warp per SMSP hides shfl/LDS latency. LDS doubles
// per SM but stays below the FMA floor (crossbar 4096 cyc, slots 2048).
//
// SMEM layouts (floats), padded so the 4 distinct per-warp LDS.128
// addresses land in disjoint bank groups:
//   sW1[d][g][36]  (32 used): j contiguous -> packed h-pairs
//   sW2[j][g][20]  (16 used): d contiguous -> packed k-pairs

#define NROWS 8192
#define TPTS  64

#define SW1_OFS 0
#define SW2_OFS 9216          // 64*144
#define SB1_OFS 19456         // + 128*80
#define SB2_OFS 19600         // + 4*36
#define SMEM_FLOATS 19680     // + 4*20

typedef unsigned long long ull;

__device__ __forceinline__ ull pack2(float a, float b) {
    ull r; asm("mov.b64 %0, {%1, %2};" : "=l"(r) : "f"(a), "f"(b)); return r;
}
__device__ __forceinline__ void unpack2(ull v, float& a, float& b) {
    asm("mov.b64 {%0, %1}, %2;" : "=f"(a), "=f"(b) : "l"(v));
}
__device__ __forceinline__ ull fma2(ull a, ull b, ull c) {
    ull d; asm("fma.rn.f32x2 %0, %1, %2, %3;" : "=l"(d) : "l"(a), "l"(b), "l"(c));
    return d;
}

__device__ __forceinline__ float tanh_fast(float x) {
    float e = __expf(2.0f * x);
    return __fdividef(e - 1.0f, e + 1.0f);
}

// y: this thread's 16-dim slice (dims [16s,16s+16)) of the stage input.
// k: this thread's 16-dim slice of f(y) (output).
__device__ __forceinline__ void eval_f(
    const float* __restrict__ sW1, const float* __restrict__ sW2,
    const float* __restrict__ sb1, const float* __restrict__ sb2,
    int q, int s, const float* y, float* k)
{
    // ---- h = b1 + W1 y, packed over j-pairs (32 j's -> 16 ull) ----
    ull h[16];
    {
        const ull* bp = (const ull*)(sb1 + s * 36);
        #pragma unroll
        for (int p = 0; p < 16; p++) h[p] = bp[p];
    }
    #pragma unroll 1
    for (int sp = 0; sp < 4; sp++) {
        int src = sp * 8 + q;
        const float* rp = sW1 + sp * (16 * 144) + s * 36;
        #pragma unroll
        for (int dd = 0; dd < 16; dd++) {
            float zv = __shfl_sync(0xffffffffu, y[dd], src);
            ull zz = pack2(zv, zv);
            const ulonglong2* w = (const ulonglong2*)(rp + dd * 144);
            #pragma unroll
            for (int m = 0; m < 8; m++) {
                ulonglong2 wv = w[m];
                h[2*m+0] = fma2(wv.x, zz, h[2*m+0]);
                h[2*m+1] = fma2(wv.y, zz, h[2*m+1]);
            }
        }
    }

    // ---- tanh (scalar) ----
    float hs[32];
    #pragma unroll
    for (int p = 0; p < 16; p++) {
        float a0, a1;
        unpack2(h[p], a0, a1);
        hs[2*p+0] = tanh_fast(a0);
        hs[2*p+1] = tanh_fast(a1);
    }

    // ---- k = b2 + W2 h, packed over d-pairs (16 d's -> 8 ull) ----
    ull kp[8];
    {
        const ull* bp = (const ull*)(sb2 + s * 20);
        #pragma unroll
        for (int p = 0; p < 8; p++) kp[p] = bp[p];
    }
    #pragma unroll 1
    for (int sp = 0; sp < 4; sp++) {
        int src = sp * 8 + q;
        const float* rp = sW2 + sp * (32 * 80) + s * 20;
        #pragma unroll
        for (int jj = 0; jj < 32; jj++) {
            float hv = __shfl_sync(0xffffffffu, hs[jj], src);
            ull dh = pack2(hv, hv);
            const ulonglong2* w = (const ulonglong2*)(rp + jj * 80);
            #pragma unroll
            for (int m = 0; m < 4; m++) {
                ulonglong2 wv = w[m];
                kp[2*m+0] = fma2(wv.x, dh, kp[2*m+0]);
                kp[2*m+1] = fma2(wv.y, dh, kp[2*m+1]);
            }
        }
    }
    #pragma unroll
    for (int p = 0; p < 8; p++)
        unpack2(kp[p], k[2*p+0], k[2*p+1]);
}

__global__ void __launch_bounds__(256, 1)
ode_kernel(const float* __restrict__ rand_e,
           const float* __restrict__ z0_mean,
           const float* __restrict__ z0_log_sigma,
           const float* __restrict__ W1,
           const float* __restrict__ b1,
           const float* __restrict__ W2,
           const float* __restrict__ b2,
           float* __restrict__ out,
           long long z0_off, long long t_off, long long z_off)
{
    extern __shared__ float sm[];
    float* sW1 = sm + SW1_OFS;
    float* sW2 = sm + SW2_OFS;
    float* sb1 = sm + SB1_OFS;
    float* sb2 = sm + SB2_OFS;
    int tid = threadIdx.x;

    // W1: (H=128, D=64) row-major -> sW1[d][j>>5][j&31]
    for (int idx = tid; idx < 128 * 64; idx += 256) {
        int j = idx >> 6, d = idx & 63;
        sW1[d * 144 + (j >> 5) * 36 + (j & 31)] = W1[idx];
    }
    // W2: (D=64, H=128) row-major -> sW2[j][d>>4][d&15]
    for (int idx = tid; idx < 64 * 128; idx += 256) {
        int d = idx >> 7, j = idx & 127;
        sW2[j * 80 + (d >> 4) * 20 + (d & 15)] = W2[idx];
    }
    if (tid < 128)      sb1[(tid >> 5) * 36 + (tid & 31)] = b1[tid];
    else if (tid < 192) { int d = tid - 128; sb2[(d >> 4) * 20 + (d & 15)] = b2[d]; }
    __syncthreads();

    int lane = tid & 31;
    int q = lane & 7;        // row within warp
    int s = lane >> 3;       // dim slice: z dims [16s,16s+16), h dims [32s,32s+32)
    int row = blockIdx.x * 64 + (tid >> 5) * 8 + q;

    if (t_off >= 0 && blockIdx.x == 0 && tid < TPTS)
        out[t_off + tid] = (float)tid * (1.0f / 63.0f);

    float sig = expf(z0_log_sigma[0]);
    float z[16];
    {
        const float4* rp = (const float4*)(rand_e + (size_t)row * 64 + s * 16);
        const float4* mp = (const float4*)(z0_mean + s * 16);
        #pragma unroll
        for (int m = 0; m < 4; m++) {
            float4 r = rp[m]; float4 zm = mp[m];
            z[4*m+0] = zm.x + sig * r.x;
            z[4*m+1] = zm.y + sig * r.y;
            z[4*m+2] = zm.z + sig * r.z;
            z[4*m+3] = zm.w + sig * r.w;
        }
    }

    size_t lofs = (size_t)row * 64 + s * 16;
    if (z0_off >= 0) {
        float4* p = (float4*)(out + z0_off + lofs);
        #pragma unroll
        for (int m = 0; m < 4; m++)
            p[m] = make_float4(z[4*m+0], z[4*m+1], z[4*m+2], z[4*m+3]);
    }
    {   // z at t=0 equals z0
        float4* p = (float4*)(out + z_off + lofs);
        #pragma unroll
        for (int m = 0; m < 4; m++)
            p[m] = make_float4(z[4*m+0], z[4*m+1], z[4*m+2], z[4*m+3]);
    }

    const float dt = 1.0f / 63.0f;
    #pragma unroll 1
    for (int step = 0; step < 63; step++) {
        float acc[16], y[16];
        #pragma unroll
        for (int i = 0; i < 16; i++) { y[i] = z[i]; acc[i] = 0.0f; }
        #pragma unroll 1
        for (int st = 0; st < 4; st++) {
            float k[16];
            eval_f(sW1, sW2, sb1, sb2, q, s, y, k);
            float bw = (st == 1 || st == 2) ? 2.0f : 1.0f;
            float aw = (st == 2) ? dt : ((st == 3) ? 0.0f : 0.5f * dt);
            #pragma unroll
            for (int i = 0; i < 16; i++) {
                acc[i] += bw * k[i];
                y[i]   = z[i] + aw * k[i];
            }
        }
        #pragma unroll
        for (int i = 0; i < 16; i++)
            z[i] += (dt * (1.0f / 6.0f)) * acc[i];

        float4* p = (float4*)(out + z_off + (size_t)(step + 1) * (NROWS * 64) + lofs);
        #pragma unroll
        for (int m = 0; m < 4; m++)
            p[m] = make_float4(z[4*m+0], z[4*m+1], z[4*m+2], z[4*m+3]);
    }
}

extern "C" void kernel_launch(void* const* d_in, const int* in_sizes, int n_in,
                              void* d_out, int out_size)
{
    const float* rand_e       = (const float*)d_in[0];
    const float* z0_mean      = (const float*)d_in[1];
    const float* z0_log_sigma = (const float*)d_in[2];
    const float* W1           = (const float*)d_in[3];
    const float* b1           = (const float*)d_in[4];
    const float* W2           = (const float*)d_in[5];
    const float* b2           = (const float*)d_in[6];

    const long long Z0SZ = (long long)NROWS * 64;   // 524288
    const long long TSZ  = TPTS;                    // 64
    const long long ZSZ  = (long long)TPTS * NROWS * 64;

    long long z0_off, t_off, z_off;
    long long osz = (long long)out_size;
    if (osz == Z0SZ + TSZ + ZSZ)      { z0_off = 0;  t_off = Z0SZ; z_off = Z0SZ + TSZ; }
    else if (osz == ZSZ)              { z0_off = -1; t_off = -1;   z_off = 0; }
    else if (osz == Z0SZ + ZSZ)       { z0_off = 0;  t_off = -1;   z_off = Z0SZ; }
    else                              { z0_off = 0;  t_off = Z0SZ; z_off = Z0SZ + TSZ; }

    cudaFuncSetAttribute(ode_kernel,
                         cudaFuncAttributeMaxDynamicSharedMemorySize,
                         SMEM_FLOATS * sizeof(float));

    ode_kernel<<<NROWS / 64, 256, SMEM_FLOATS * sizeof(float)>>>(
        rand_e, z0_mean, z0_log_sigma, W1, b1, W2, b2,
        (float*)d_out, z0_off, t_off, z_off);
}

// round 6
// speedup vs baseline: 1.3761x; 1.3761x over previous
#include <cuda_runtime.h>
#include <cstdint>

// GenODE: z' = tanh(z W1^T + b1) W2^T + b2, N=8192 rows, D=64, H=128.
// Fixed-step RK4, dt = 1/63, one step per output interval.
//
// R6: 8 threads per row-group, 2 rows per thread, 256 threads/CTA (8 warps,
// 2/SMSP), 64 rows/CTA, grid=128.
//   - FMA2:LDS.128 ratio 4:1 (weight loads reused across 2 rows and packed
//     fma.rn.f32x2 along the output dim) -> 4096 LDS.128/SM/eval, at the
//     measured ~2cyc/LDS.128 LSU cost this matches the 8192-cyc FMA2 floor.
//   - 2 warps/SMSP hides shfl/LDS/MUFU latency (R4's failure mode).
//
// Thread map: lane = s*4 + g; s in 0..7 owns z dims [8s,8s+8) and h dims
// [16s,16s+16); g in 0..3 selects the row pair. Warp holds 8 rows
// (4 groups x 2). Lanes sharing s (4 of them) read identical SMEM weight
// addresses (broadcast); the 8 distinct 16B addresses per warp-LDS land in
// the 8 disjoint bank groups via slice strides 20 (W1) and 12 (W2).

#define NROWS 8192
#define TPTS  64

#define R1 160                // W1 row stride (floats): 8 slices * 20
#define S1 20                 // W1 slice stride
#define R2 96                 // W2 row stride: 8 slices * 12
#define S2 12                 // W2 slice stride

#define SW1_OFS 0
#define SW2_OFS 10240         // 64*160
#define SB1_OFS 22528         // + 128*96
#define SB2_OFS 22688         // + 8*20
#define SMEM_FLOATS 22784     // + 8*12

typedef unsigned long long ull;

__device__ __forceinline__ ull pack2(float a, float b) {
    ull r; asm("mov.b64 %0, {%1, %2};" : "=l"(r) : "f"(a), "f"(b)); return r;
}
__device__ __forceinline__ void unpack2(ull v, float& a, float& b) {
    asm("mov.b64 {%0, %1}, %2;" : "=f"(a), "=f"(b) : "l"(v));
}
__device__ __forceinline__ ull fma2(ull a, ull b, ull c) {
    ull d; asm("fma.rn.f32x2 %0, %1, %2, %3;" : "=l"(d) : "l"(a), "l"(b), "l"(c));
    return d;
}

__device__ __forceinline__ float tanh_fast(float x) {
    float e = __expf(2.0f * x);
    return __fdividef(e - 1.0f, e + 1.0f);
}

// yA/yB: 8-dim slices (z dims [8s,8s+8)) of the stage input, rows A and B.
// kA/kB: 8-dim slices of f(y).
__device__ __forceinline__ void eval2(
    const float* __restrict__ sW1, const float* __restrict__ sW2,
    const float* __restrict__ sb1, const float* __restrict__ sb2,
    int g, int s,
    const float* yA, const float* yB, float* kA, float* kB)
{
    // ---- h = b1 + W1 y : 16 h's per thread = 8 packed pairs per row ----
    ull hA[8], hB[8];
    {
        const ull* bp = (const ull*)(sb1 + s * S1);
        #pragma unroll
        for (int p = 0; p < 8; p++) { hA[p] = bp[p]; hB[p] = bp[p]; }
    }
    #pragma unroll 1
    for (int sp = 0; sp < 8; sp++) {
        int src = sp * 4 + g;
        const float* rp = sW1 + (sp * 8) * R1 + s * S1;
        #pragma unroll
        for (int dd = 0; dd < 8; dd++) {
            float zA = __shfl_sync(0xffffffffu, yA[dd], src);
            float zB = __shfl_sync(0xffffffffu, yB[dd], src);
            ull zzA = pack2(zA, zA);
            ull zzB = pack2(zB, zB);
            const ulonglong2* w = (const ulonglong2*)(rp + dd * R1);
            #pragma unroll
            for (int m = 0; m < 4; m++) {
                ulonglong2 wv = w[m];
                hA[2*m+0] = fma2(wv.x, zzA, hA[2*m+0]);
                hA[2*m+1] = fma2(wv.y, zzA, hA[2*m+1]);
                hB[2*m+0] = fma2(wv.x, zzB, hB[2*m+0]);
                hB[2*m+1] = fma2(wv.y, zzB, hB[2*m+1]);
            }
        }
    }

    // ---- tanh (scalar) ----
    float hsA[16], hsB[16];
    #pragma unroll
    for (int p = 0; p < 8; p++) {
        float a0, a1, b0, b1v;
        unpack2(hA[p], a0, a1);
        unpack2(hB[p], b0, b1v);
        hsA[2*p+0] = tanh_fast(a0);
        hsA[2*p+1] = tanh_fast(a1);
        hsB[2*p+0] = tanh_fast(b0);
        hsB[2*p+1] = tanh_fast(b1v);
    }

    // ---- k = b2 + W2 h : 8 k's per thread = 4 packed pairs per row ----
    ull kpA[4], kpB[4];
    {
        const ull* bp = (const ull*)(sb2 + s * S2);
        #pragma unroll
        for (int p = 0; p < 4; p++) { kpA[p] = bp[p]; kpB[p] = bp[p]; }
    }
    #pragma unroll 1
    for (int sp = 0; sp < 8; sp++) {
        int src = sp * 4 + g;
        const float* rp = sW2 + (sp * 16) * R2 + s * S2;
        #pragma unroll
        for (int jj = 0; jj < 16; jj++) {
            float ha = __shfl_sync(0xffffffffu, hsA[jj], src);
            float hb = __shfl_sync(0xffffffffu, hsB[jj], src);
            ull da = pack2(ha, ha);
            ull db = pack2(hb, hb);
            const ulonglong2* w = (const ulonglong2*)(rp + jj * R2);
            #pragma unroll
            for (int m = 0; m < 2; m++) {
                ulonglong2 wv = w[m];
                kpA[2*m+0] = fma2(wv.x, da, kpA[2*m+0]);
                kpA[2*m+1] = fma2(wv.y, da, kpA[2*m+1]);
                kpB[2*m+0] = fma2(wv.x, db, kpB[2*m+0]);
                kpB[2*m+1] = fma2(wv.y, db, kpB[2*m+1]);
            }
        }
    }
    #pragma unroll
    for (int p = 0; p < 4; p++) {
        unpack2(kpA[p], kA[2*p+0], kA[2*p+1]);
        unpack2(kpB[p], kB[2*p+0], kB[2*p+1]);
    }
}

__global__ void __launch_bounds__(256, 1)
ode_kernel(const float* __restrict__ rand_e,
           const float* __restrict__ z0_mean,
           const float* __restrict__ z0_log_sigma,
           const float* __restrict__ W1,
           const float* __restrict__ b1,
           const float* __restrict__ W2,
           const float* __restrict__ b2,
           float* __restrict__ out,
           long long z0_off, long long t_off, long long z_off)
{
    extern __shared__ float sm[];
    float* sW1 = sm + SW1_OFS;
    float* sW2 = sm + SW2_OFS;
    float* sb1 = sm + SB1_OFS;
    float* sb2 = sm + SB2_OFS;
    int tid = threadIdx.x;

    // W1: (H=128, D=64) row-major -> sW1[d*R1 + (j>>4)*S1 + (j&15)]
    for (int idx = tid; idx < 128 * 64; idx += 256) {
        int j = idx >> 6, d = idx & 63;
        sW1[d * R1 + (j >> 4) * S1 + (j & 15)] = W1[idx];
    }
    // W2: (D=64, H=128) row-major -> sW2[j*R2 + (d>>3)*S2 + (d&7)]
    for (int idx = tid; idx < 64 * 128; idx += 256) {
        int d = idx >> 7, j = idx & 127;
        sW2[j * R2 + (d >> 3) * S2 + (d & 7)] = W2[idx];
    }
    if (tid < 128)      sb1[(tid >> 4) * S1 + (tid & 15)] = b1[tid];
    else if (tid < 192) { int d = tid - 128; sb2[(d >> 3) * S2 + (d & 7)] = b2[d]; }
    __syncthreads();

    int lane = tid & 31;
    int g = lane & 3;        // row-pair group within warp
    int s = lane >> 2;       // dim slice: z dims [8s,8s+8), h dims [16s,16s+16)
    int warp = tid >> 5;
    int rowA = blockIdx.x * 64 + warp * 8 + g;
    int rowB = rowA + 4;

    if (t_off >= 0 && blockIdx.x == 0 && tid < TPTS)
        out[t_off + tid] = (float)tid * (1.0f / 63.0f);

    float sig = expf(z0_log_sigma[0]);
    float zA[8], zB[8];
    {
        const float4* rA = (const float4*)(rand_e + (size_t)rowA * 64 + s * 8);
        const float4* rB = (const float4*)(rand_e + (size_t)rowB * 64 + s * 8);
        const float4* mp = (const float4*)(z0_mean + s * 8);
        #pragma unroll
        for (int m = 0; m < 2; m++) {
            float4 ra = rA[m]; float4 rb = rB[m]; float4 zm = mp[m];
            zA[4*m+0] = zm.x + sig * ra.x; zA[4*m+1] = zm.y + sig * ra.y;
            zA[4*m+2] = zm.z + sig * ra.z; zA[4*m+3] = zm.w + sig * ra.w;
            zB[4*m+0] = zm.x + sig * rb.x; zB[4*m+1] = zm.y + sig * rb.y;
            zB[4*m+2] = zm.z + sig * rb.z; zB[4*m+3] = zm.w + sig * rb.w;
        }
    }

    size_t lofsA = (size_t)rowA * 64 + s * 8;
    size_t lofsB = (size_t)rowB * 64 + s * 8;
    if (z0_off >= 0) {
        float4* pA = (float4*)(out + z0_off + lofsA);
        float4* pB = (float4*)(out + z0_off + lofsB);
        #pragma unroll
        for (int m = 0; m < 2; m++) {
            pA[m] = make_float4(zA[4*m+0], zA[4*m+1], zA[4*m+2], zA[4*m+3]);
            pB[m] = make_float4(zB[4*m+0], zB[4*m+1], zB[4*m+2], zB[4*m+3]);
        }
    }
    {   // z at t=0 equals z0
        float4* pA = (float4*)(out + z_off + lofsA);
        float4* pB = (float4*)(out + z_off + lofsB);
        #pragma unroll
        for (int m = 0; m < 2; m++) {
            pA[m] = make_float4(zA[4*m+0], zA[4*m+1], zA[4*m+2], zA[4*m+3]);
            pB[m] = make_float4(zB[4*m+0], zB[4*m+1], zB[4*m+2], zB[4*m+3]);
        }
    }

    const float dt = 1.0f / 63.0f;
    #pragma unroll 1
    for (int step = 0; step < 63; step++) {
        float accA[8], accB[8], yA[8], yB[8];
        #pragma unroll
        for (int i = 0; i < 8; i++) {
            yA[i] = zA[i]; yB[i] = zB[i];
            accA[i] = 0.0f; accB[i] = 0.0f;
        }
        #pragma unroll 1
        for (int st = 0; st < 4; st++) {
            float kA[8], kB[8];
            eval2(sW1, sW2, sb1, sb2, g, s, yA, yB, kA, kB);
            float bw = (st == 1 || st == 2) ? 2.0f : 1.0f;
            float aw = (st == 2) ? dt : ((st == 3) ? 0.0f : 0.5f * dt);
            #pragma unroll
            for (int i = 0; i < 8; i++) {
                accA[i] += bw * kA[i];
                accB[i] += bw * kB[i];
                yA[i]   = zA[i] + aw * kA[i];
                yB[i]   = zB[i] + aw * kB[i];
            }
        }
        #pragma unroll
        for (int i = 0; i < 8; i++) {
            zA[i] += (dt * (1.0f / 6.0f)) * accA[i];
            zB[i] += (dt * (1.0f / 6.0f)) * accB[i];
        }

        size_t tofs = z_off + (size_t)(step + 1) * (NROWS * 64);
        float4* pA = (float4*)(out + tofs + lofsA);
        float4* pB = (float4*)(out + tofs + lofsB);
        #pragma unroll
        for (int m = 0; m < 2; m++) {
            pA[m] = make_float4(zA[4*m+0], zA[4*m+1], zA[4*m+2], zA[4*m+3]);
            pB[m] = make_float4(zB[4*m+0], zB[4*m+1], zB[4*m+2], zB[4*m+3]);
        }
    }
}

extern "C" void kernel_launch(void* const* d_in, const int* in_sizes, int n_in,
                              void* d_out, int out_size)
{
    const float* rand_e       = (const float*)d_in[0];
    const float* z0_mean      = (const float*)d_in[1];
    const float* z0_log_sigma = (const float*)d_in[2];
    const float* W1           = (const float*)d_in[3];
    const float* b1           = (const float*)d_in[4];
    const float* W2           = (const float*)d_in[5];
    const float* b2           = (const float*)d_in[6];

    const long long Z0SZ = (long long)NROWS * 64;   // 524288
    const long long TSZ  = TPTS;                    // 64
    const long long ZSZ  = (long long)TPTS * NROWS * 64;

    long long z0_off, t_off, z_off;
    long long osz = (long long)out_size;
    if (osz == Z0SZ + TSZ + ZSZ)      { z0_off = 0;  t_off = Z0SZ; z_off = Z0SZ + TSZ; }
    else if (osz == ZSZ)              { z0_off = -1; t_off = -1;   z_off = 0; }
    else if (osz == Z0SZ + ZSZ)       { z0_off = 0;  t_off = -1;   z_off = Z0SZ; }
    else                              { z0_off = 0;  t_off = Z0SZ; z_off = Z0SZ + TSZ; }

    cudaFuncSetAttribute(ode_kernel,
                         cudaFuncAttributeMaxDynamicSharedMemorySize,
                         SMEM_FLOATS * sizeof(float));

    ode_kernel<<<NROWS / 64, 256, SMEM_FLOATS * sizeof(float)>>>(
        rand_e, z0_mean, z0_log_sigma, W1, b1, W2, b2,
        (float*)d_out, z0_off, t_off, z_off);
}

// round 8
// speedup vs baseline: 1.4100x; 1.0246x over previous
#include <cuda_runtime.h>
#include <cstdint>

// GenODE: z' = tanh(z W1^T + b1) W2^T + b2, N=8192 rows, D=64, H=128.
// Fixed-step RK4, dt = 1/63, one step per output interval.
//
// R7 = R6 (P=8 threads/row, rpt=2 rows/thread, 256 thr/CTA, grid=128)
//      with SHFL broadcast replaced by per-warp SMEM staging:
//  * each thread stores its y slice / tanh(h) slice to a padded per-warp
//    buffer, __syncwarp, then vector-loads (LDS.128) full rows in chunks.
//  * MIO ops per warp per eval: 384 shfl -> 96 LDS.128 + 12 STS.128.
//    MIO/SM/eval ~5000 cyc, below the 8192-cyc fma.rn.f32x2 pipe floor.
//  * warp is non-divergent -> lockstep; 2x __syncwarp per eval orders SMEM.
//
// Weight SMEM layouts (floats), slice strides chosen so the 8 distinct
// 16B addresses per warp-LDS land in 8 disjoint bank groups:
//   sW1[d*160 + (j/16)*20 + j%16],  sW2[j*96 + (d/8)*12 + d%8]
// Exchange buffers: y rows stride 68, h rows stride 132 (bank-spread).

#define NROWS 8192
#define TPTS  64

#define R1 160
#define S1 20
#define R2 96
#define S2 12

#define SW1_OFS 0
#define SW2_OFS 10240         // 64*160
#define SB1_OFS 22528         // + 128*96
#define SB2_OFS 22688         // + 8*20
#define YB_OFS  22784         // + 8*12
#define HB_OFS  27136         // + 8 warps * 544
#define SMEM_FLOATS 35584     // + 8 warps * 1056

typedef unsigned long long ull;

__device__ __forceinline__ ull pack2(float a, float b) {
    ull r; asm("mov.b64 %0, {%1, %2};" : "=l"(r) : "f"(a), "f"(b)); return r;
}
__device__ __forceinline__ void unpack2(ull v, float& a, float& b) {
    asm("mov.b64 {%0, %1}, %2;" : "=f"(a), "=f"(b) : "l"(v));
}
__device__ __forceinline__ ull fma2(ull a, ull b, ull c) {
    ull d; asm("fma.rn.f32x2 %0, %1, %2, %3;" : "=l"(d) : "l"(a), "l"(b), "l"(c));
    return d;
}

__device__ __forceinline__ float tanh_fast(float x) {
    float e = __expf(2.0f * x);
    return __fdividef(e - 1.0f, e + 1.0f);
}

// yA/yB: 8-dim slices (z dims [8s,8s+8)) of the stage input, rows g and g+4.
// kA/kB: 8-dim slices of f(y).
__device__ __forceinline__ void eval2(
    const float* __restrict__ sW1, const float* __restrict__ sW2,
    const float* __restrict__ sb1, const float* __restrict__ sb2,
    float* __restrict__ yb, float* __restrict__ hb,
    int g, int s,
    const float* yA, const float* yB, float* kA, float* kB)
{
    // ---- stage y slices to per-warp SMEM ----
    {
        float4* pA = (float4*)(yb + g * 68 + s * 8);
        float4* pB = (float4*)(yb + (g + 4) * 68 + s * 8);
        pA[0] = make_float4(yA[0], yA[1], yA[2], yA[3]);
        pA[1] = make_float4(yA[4], yA[5], yA[6], yA[7]);
        pB[0] = make_float4(yB[0], yB[1], yB[2], yB[3]);
        pB[1] = make_float4(yB[4], yB[5], yB[6], yB[7]);
    }
    __syncwarp();

    // ---- h = b1 + W1 y : 16 h's per thread per row = 8 packed pairs ----
    ull hA[8], hB[8];
    {
        const ull* bp = (const ull*)(sb1 + s * S1);
        #pragma unroll
        for (int p = 0; p < 8; p++) { hA[p] = bp[p]; hB[p] = bp[p]; }
    }
    {
        const float*  wr  = sW1 + s * S1;
        const float4* yrA = (const float4*)(yb + g * 68);
        const float4* yrB = (const float4*)(yb + (g + 4) * 68);
        #pragma unroll 2
        for (int c = 0; c < 16; c++) {
            float4 a4 = yrA[c];
            float4 b4 = yrB[c];
            float av[4] = {a4.x, a4.y, a4.z, a4.w};
            float bv[4] = {b4.x, b4.y, b4.z, b4.w};
            #pragma unroll
            for (int t = 0; t < 4; t++) {
                ull zzA = pack2(av[t], av[t]);
                ull zzB = pack2(bv[t], bv[t]);
                const ulonglong2* w = (const ulonglong2*)(wr + (c * 4 + t) * R1);
                ulonglong2 w0 = w[0], w1 = w[1], w2 = w[2], w3 = w[3];
                hA[0] = fma2(w0.x, zzA, hA[0]); hA[1] = fma2(w0.y, zzA, hA[1]);
                hA[2] = fma2(w1.x, zzA, hA[2]); hA[3] = fma2(w1.y, zzA, hA[3]);
                hA[4] = fma2(w2.x, zzA, hA[4]); hA[5] = fma2(w2.y, zzA, hA[5]);
                hA[6] = fma2(w3.x, zzA, hA[6]); hA[7] = fma2(w3.y, zzA, hA[7]);
                hB[0] = fma2(w0.x, zzB, hB[0]); hB[1] = fma2(w0.y, zzB, hB[1]);
                hB[2] = fma2(w1.x, zzB, hB[2]); hB[3] = fma2(w1.y, zzB, hB[3]);
                hB[4] = fma2(w2.x, zzB, hB[4]); hB[5] = fma2(w2.y, zzB, hB[5]);
                hB[6] = fma2(w3.x, zzB, hB[6]); hB[7] = fma2(w3.y, zzB, hB[7]);
            }
        }
    }

    // ---- tanh, stage h slices to per-warp SMEM ----
    {
        float hsA[16], hsB[16];
        #pragma unroll
        for (int p = 0; p < 8; p++) {
            float a0, a1, b0, b1v;
            unpack2(hA[p], a0, a1);
            unpack2(hB[p], b0, b1v);
            hsA[2*p+0] = tanh_fast(a0);
            hsA[2*p+1] = tanh_fast(a1);
            hsB[2*p+0] = tanh_fast(b0);
            hsB[2*p+1] = tanh_fast(b1v);
        }
        float4* qA = (float4*)(hb + g * 132 + s * 16);
        float4* qB = (float4*)(hb + (g + 4) * 132 + s * 16);
        #pragma unroll
        for (int m = 0; m < 4; m++) {
            qA[m] = make_float4(hsA[4*m+0], hsA[4*m+1], hsA[4*m+2], hsA[4*m+3]);
            qB[m] = make_float4(hsB[4*m+0], hsB[4*m+1], hsB[4*m+2], hsB[4*m+3]);
        }
    }
    __syncwarp();

    // ---- k = b2 + W2 h : 8 k's per thread per row = 4 packed pairs ----
    ull kpA[4], kpB[4];
    {
        const ull* bp = (const ull*)(sb2 + s * S2);
        #pragma unroll
        for (int p = 0; p < 4; p++) { kpA[p] = bp[p]; kpB[p] = bp[p]; }
    }
    {
        const float*  wr  = sW2 + s * S2;
        const float4* hrA = (const float4*)(hb + g * 132);
        const float4* hrB = (const float4*)(hb + (g + 4) * 132);
        #pragma unroll 4
        for (int c = 0; c < 32; c++) {
            float4 a4 = hrA[c];
            float4 b4 = hrB[c];
            float av[4] = {a4.x, a4.y, a4.z, a4.w};
            float bv[4] = {b4.x, b4.y, b4.z, b4.w};
            #pragma unroll
            for (int t = 0; t < 4; t++) {
                ull da = pack2(av[t], av[t]);
                ull db = pack2(bv[t], bv[t]);
                const ulonglong2* w = (const ulonglong2*)(wr + (c * 4 + t) * R2);
                ulonglong2 w0 = w[0], w1 = w[1];
                kpA[0] = fma2(w0.x, da, kpA[0]); kpA[1] = fma2(w0.y, da, kpA[1]);
                kpA[2] = fma2(w1.x, da, kpA[2]); kpA[3] = fma2(w1.y, da, kpA[3]);
                kpB[0] = fma2(w0.x, db, kpB[0]); kpB[1] = fma2(w0.y, db, kpB[1]);
                kpB[2] = fma2(w1.x, db, kpB[2]); kpB[3] = fma2(w1.y, db, kpB[3]);
            }
        }
    }
    #pragma unroll
    for (int p = 0; p < 4; p++) {
        unpack2(kpA[p], kA[2*p+0], kA[2*p+1]);
        unpack2(kpB[p], kB[2*p+0], kB[2*p+1]);
    }
}

__global__ void __launch_bounds__(256, 1)
ode_kernel(const float* __restrict__ rand_e,
           const float* __restrict__ z0_mean,
           const float* __restrict__ z0_log_sigma,
           const float* __restrict__ W1,
           const float* __restrict__ b1,
           const float* __restrict__ W2,
           const float* __restrict__ b2,
           float* __restrict__ out,
           long long z0_off, long long t_off, long long z_off)
{
    extern __shared__ float sm[];
    float* sW1 = sm + SW1_OFS;
    float* sW2 = sm + SW2_OFS;
    float* sb1 = sm + SB1_OFS;
    float* sb2 = sm + SB2_OFS;
    int tid = threadIdx.x;

    // W1: (H=128, D=64) row-major -> sW1[d*R1 + (j>>4)*S1 + (j&15)]
    for (int idx = tid; idx < 128 * 64; idx += 256) {
        int j = idx >> 6, d = idx & 63;
        sW1[d * R1 + (j >> 4) * S1 + (j & 15)] = W1[idx];
    }
    // W2: (D=64, H=128) row-major -> sW2[j*R2 + (d>>3)*S2 + (d&7)]
    for (int idx = tid; idx < 64 * 128; idx += 256) {
        int d = idx >> 7, j = idx & 127;
        sW2[j * R2 + (d >> 3) * S2 + (d & 7)] = W2[idx];
    }
    if (tid < 128)      sb1[(tid >> 4) * S1 + (tid & 15)] = b1[tid];
    else if (tid < 192) { int d = tid - 128; sb2[(d >> 3) * S2 + (d & 7)] = b2[d]; }
    __syncthreads();

    int lane = tid & 31;
    int g = lane & 3;        // row-pair group within warp
    int s = lane >> 2;       // dim slice: z dims [8s,8s+8), h dims [16s,16s+16)
    int warp = tid >> 5;
    float* yb = sm + YB_OFS + warp * 544;    // 8 rows * 68
    float* hb = sm + HB_OFS + warp * 1056;   // 8 rows * 132
    int rowA = blockIdx.x * 64 + warp * 8 + g;
    int rowB = rowA + 4;

    if (t_off >= 0 && blockIdx.x == 0 && tid < TPTS)
        out[t_off + tid] = (float)tid * (1.0f / 63.0f);

    float sig = expf(z0_log_sigma[0]);
    float zA[8], zB[8];
    {
        const float4* rA = (const float4*)(rand_e + (size_t)rowA * 64 + s * 8);
        const float4* rB = (const float4*)(rand_e + (size_t)rowB * 64 + s * 8);
        const float4* mp = (const float4*)(z0_mean + s * 8);
        #pragma unroll
        for (int m = 0; m < 2; m++) {
            float4 ra = rA[m]; float4 rb = rB[m]; float4 zm = mp[m];
            zA[4*m+0] = zm.x + sig * ra.x; zA[4*m+1] = zm.y + sig * ra.y;
            zA[4*m+2] = zm.z + sig * ra.z; zA[4*m+3] = zm.w + sig * ra.w;
            zB[4*m+0] = zm.x + sig * rb.x; zB[4*m+1] = zm.y + sig * rb.y;
            zB[4*m+2] = zm.z + sig * rb.z; zB[4*m+3] = zm.w + sig * rb.w;
        }
    }

    size_t lofsA = (size_t)rowA * 64 + s * 8;
    size_t lofsB = (size_t)rowB * 64 + s * 8;
    if (z0_off >= 0) {
        float4* pA = (float4*)(out + z0_off + lofsA);
        float4* pB = (float4*)(out + z0_off + lofsB);
        #pragma unroll
        for (int m = 0; m < 2; m++) {
            pA[m] = make_float4(zA[4*m+0], zA[4*m+1], zA[4*m+2], zA[4*m+3]);
            pB[m] = make_float4(zB[4*m+0], zB[4*m+1], zB[4*m+2], zB[4*m+3]);
        }
    }
    {   // z at t=0 equals z0
        float4* pA = (float4*)(out + z_off + lofsA);
        float4* pB = (float4*)(out + z_off + lofsB);
        #pragma unroll
        for (int m = 0; m < 2; m++) {
            pA[m] = make_float4(zA[4*m+0], zA[4*m+1], zA[4*m+2], zA[4*m+3]);
            pB[m] = make_float4(zB[4*m+0], zB[4*m+1], zB[4*m+2], zB[4*m+3]);
        }
    }

    const float dt = 1.0f / 63.0f;
    #pragma unroll 1
    for (int step = 0; step < 63; step++) {
        float accA[8], accB[8], yA[8], yB[8];
        #pragma unroll
        for (int i = 0; i < 8; i++) {
            yA[i] = zA[i]; yB[i] = zB[i];
            accA[i] = 0.0f; accB[i] = 0.0f;
        }
        #pragma unroll 1
        for (int st = 0; st < 4; st++) {
            float kA[8], kB[8];
            eval2(sW1, sW2, sb1, sb2, yb, hb, g, s, yA, yB, kA, kB);
            float bw = (st == 1 || st == 2) ? 2.0f : 1.0f;
            float aw = (st == 2) ? dt : ((st == 3) ? 0.0f : 0.5f * dt);
            #pragma unroll
            for (int i = 0; i < 8; i++) {
                accA[i] += bw * kA[i];
                accB[i] += bw * kB[i];
                yA[i]   = zA[i] + aw * kA[i];
                yB[i]   = zB[i] + aw * kB[i];
            }
        }
        #pragma unroll
        for (int i = 0; i < 8; i++) {
            zA[i] += (dt * (1.0f / 6.0f)) * accA[i];
            zB[i] += (dt * (1.0f / 6.0f)) * accB[i];
        }

        size_t tofs = z_off + (size_t)(step + 1) * (NROWS * 64);
        float4* pA = (float4*)(out + tofs + lofsA);
        float4* pB = (float4*)(out + tofs + lofsB);
        #pragma unroll
        for (int m = 0; m < 2; m++) {
            pA[m] = make_float4(zA[4*m+0], zA[4*m+1], zA[4*m+2], zA[4*m+3]);
            pB[m] = make_float4(zB[4*m+0], zB[4*m+1], zB[4*m+2], zB[4*m+3]);
        }
    }
}

extern "C" void kernel_launch(void* const* d_in, const int* in_sizes, int n_in,
                              void* d_out, int out_size)
{
    const float* rand_e       = (const float*)d_in[0];
    const float* z0_mean      = (const float*)d_in[1];
    const float* z0_log_sigma = (const float*)d_in[2];
    const float* W1           = (const float*)d_in[3];
    const float* b1           = (const float*)d_in[4];
    const float* W2           = (const float*)d_in[5];
    const float* b2           = (const float*)d_in[6];

    const long long Z0SZ = (long long)NROWS * 64;   // 524288
    const long long TSZ  = TPTS;                    // 64
    const long long ZSZ  = (long long)TPTS * NROWS * 64;

    long long z0_off, t_off, z_off;
    long long osz = (long long)out_size;
    if (osz == Z0SZ + TSZ + ZSZ)      { z0_off = 0;  t_off = Z0SZ; z_off = Z0SZ + TSZ; }
    else if (osz == ZSZ)              { z0_off = -1; t_off = -1;   z_off = 0; }
    else if (osz == Z0SZ + ZSZ)       { z0_off = 0;  t_off = -1;   z_off = Z0SZ; }
    else                              { z0_off = 0;  t_off = Z0SZ; z_off = Z0SZ + TSZ; }

    cudaFuncSetAttribute(ode_kernel,
                         cudaFuncAttributeMaxDynamicSharedMemorySize,
                         SMEM_FLOATS * sizeof(float));

    ode_kernel<<<NROWS / 64, 256, SMEM_FLOATS * sizeof(float)>>>(
        rand_e, z0_mean, z0_log_sigma, W1, b1, W2, b2,
        (float*)d_out, z0_off, t_off, z_off);
}

// round 9
// speedup vs baseline: 1.5636x; 1.1090x over previous
#include <cuda_runtime.h>
#include <cstdint>

// GenODE: z' = tanh(z W1^T + b1) W2^T + b2, N=8192 rows, D=64, H=128.
// Fixed-step RK4, dt = 1/63, one step per output interval.
//
// R9: P=16 threads/row, rpt=4 rows/thread, 256 thr/CTA (8 warps), 64
// rows/CTA, grid=128. Each weight LDS.128 now feeds 4 rows (8 packed
// fma.rn.f32x2 for W1, 8 for W2 per 2/1 loads) -> weight LDS per SM per
// eval halves to 2048; total MIO ~3700/SM/eval (~6700 L1 cyc at the
// measured ~1.8cyc/LDS.128), below the 8192-cyc FMA2 pipe floor.
// Exchange via per-warp SMEM staging (R7 scheme), 2 __syncwarp per eval.
//
// Thread map: lane = s*2 + g? -> s = lane>>1 (0..15), g = lane&1.
// Thread owns, per row, z dims [4s,4s+4) and h dims [8s,8s+8); its 4 rows
// are (warp base) + g + 2i, i=0..3.
//
// Weight SMEM: sW1[d*192 + (j>>3)*12 + (j&7)] (slice stride 12: the 16
// distinct per-warp 16B addresses s*12 mod 128B cover all 8 bank groups
// twice -> 2 clean wavefronts). sW2[j*64 + d] (stride 4, same property).
// Exchange: yb row stride 68, hb row stride 132 (paired rows 4 banks apart).

#define NROWS 8192
#define TPTS  64

#define SW1_OFS 0
#define SW2_OFS 12288         // 64*192
#define SB1_OFS 20480         // + 128*64
#define SB2_OFS 20672         // + 16*12
#define YB_OFS  20736         // + 64
#define HB_OFS  25088         // + 8 warps * 544
#define SMEM_FLOATS 33536     // + 8 warps * 1056

typedef unsigned long long ull;

__device__ __forceinline__ ull pack2(float a, float b) {
    ull r; asm("mov.b64 %0, {%1, %2};" : "=l"(r) : "f"(a), "f"(b)); return r;
}
__device__ __forceinline__ void unpack2(ull v, float& a, float& b) {
    asm("mov.b64 {%0, %1}, %2;" : "=f"(a), "=f"(b) : "l"(v));
}
__device__ __forceinline__ ull fma2(ull a, ull b, ull c) {
    ull d; asm("fma.rn.f32x2 %0, %1, %2, %3;" : "=l"(d) : "l"(a), "l"(b), "l"(c));
    return d;
}

__device__ __forceinline__ float tanh_fast(float x) {
    float e = __expf(2.0f * x);
    return __fdividef(e - 1.0f, e + 1.0f);
}

// y[i][0..3]: z-slice (dims [4s,4s+4)) of stage input for row i of this
// thread's 4 rows. k[i][0..3]: f(y) slice out.
__device__ __forceinline__ void eval4(
    const float* __restrict__ sW1, const float* __restrict__ sW2,
    const float* __restrict__ sb1, const float* __restrict__ sb2,
    float* __restrict__ yb, float* __restrict__ hb,
    int g, int s,
    const float y[4][4], float k[4][4])
{
    // ---- stage y slices ----
    #pragma unroll
    for (int i = 0; i < 4; i++) {
        int r = g + 2 * i;
        *(float4*)(yb + r * 68 + s * 4) =
            make_float4(y[i][0], y[i][1], y[i][2], y[i][3]);
    }
    __syncwarp();

    // ---- h = b1 + W1 y : 8 h per thread per row = 4 ull x 4 rows ----
    ull h[4][4];
    {
        const ull* bp = (const ull*)(sb1 + s * 12);
        ull b0 = bp[0], b1v = bp[1], b2v = bp[2], b3 = bp[3];
        #pragma unroll
        for (int i = 0; i < 4; i++) {
            h[i][0] = b0; h[i][1] = b1v; h[i][2] = b2v; h[i][3] = b3;
        }
    }
    {
        const float* wr = sW1 + s * 12;
        #pragma unroll 4
        for (int c = 0; c < 16; c++) {
            float4 yv[4];
            #pragma unroll
            for (int i = 0; i < 4; i++)
                yv[i] = *(const float4*)(yb + (g + 2 * i) * 68 + c * 4);
            #pragma unroll
            for (int t = 0; t < 4; t++) {
                const ulonglong2* w = (const ulonglong2*)(wr + (c * 4 + t) * 192);
                ulonglong2 w0 = w[0], w1 = w[1];
                #pragma unroll
                for (int i = 0; i < 4; i++) {
                    float zv = (t == 0) ? yv[i].x : (t == 1) ? yv[i].y
                             : (t == 2) ? yv[i].z : yv[i].w;
                    ull zz = pack2(zv, zv);
                    h[i][0] = fma2(w0.x, zz, h[i][0]);
                    h[i][1] = fma2(w0.y, zz, h[i][1]);
                    h[i][2] = fma2(w1.x, zz, h[i][2]);
                    h[i][3] = fma2(w1.y, zz, h[i][3]);
                }
            }
        }
    }

    // ---- tanh, stage h slices ----
    #pragma unroll
    for (int i = 0; i < 4; i++) {
        float hs[8];
        #pragma unroll
        for (int p = 0; p < 4; p++) {
            float a, b;
            unpack2(h[i][p], a, b);
            hs[2*p+0] = tanh_fast(a);
            hs[2*p+1] = tanh_fast(b);
        }
        float4* q = (float4*)(hb + (g + 2 * i) * 132 + s * 8);
        q[0] = make_float4(hs[0], hs[1], hs[2], hs[3]);
        q[1] = make_float4(hs[4], hs[5], hs[6], hs[7]);
    }
    __syncwarp();

    // ---- k = b2 + W2 h : 4 k per thread per row = 2 ull x 4 rows ----
    ull kp[4][2];
    {
        const ull* bp = (const ull*)(sb2 + s * 4);
        ull b0 = bp[0], b1v = bp[1];
        #pragma unroll
        for (int i = 0; i < 4; i++) { kp[i][0] = b0; kp[i][1] = b1v; }
    }
    {
        const float* wr = sW2 + s * 4;
        #pragma unroll 4
        for (int c = 0; c < 32; c++) {
            float4 hv[4];
            #pragma unroll
            for (int i = 0; i < 4; i++)
                hv[i] = *(const float4*)(hb + (g + 2 * i) * 132 + c * 4);
            #pragma unroll
            for (int t = 0; t < 4; t++) {
                const ulonglong2* w = (const ulonglong2*)(wr + (c * 4 + t) * 64);
                ulonglong2 w0 = w[0];
                #pragma unroll
                for (int i = 0; i < 4; i++) {
                    float hvv = (t == 0) ? hv[i].x : (t == 1) ? hv[i].y
                              : (t == 2) ? hv[i].z : hv[i].w;
                    ull dh = pack2(hvv, hvv);
                    kp[i][0] = fma2(w0.x, dh, kp[i][0]);
                    kp[i][1] = fma2(w0.y, dh, kp[i][1]);
                }
            }
        }
    }
    #pragma unroll
    for (int i = 0; i < 4; i++) {
        unpack2(kp[i][0], k[i][0], k[i][1]);
        unpack2(kp[i][1], k[i][2], k[i][3]);
    }
}

__global__ void __launch_bounds__(256, 1)
ode_kernel(const float* __restrict__ rand_e,
           const float* __restrict__ z0_mean,
           const float* __restrict__ z0_log_sigma,
           const float* __restrict__ W1,
           const float* __restrict__ b1,
           const float* __restrict__ W2,
           const float* __restrict__ b2,
           float* __restrict__ out,
           long long z0_off, long long t_off, long long z_off)
{
    extern __shared__ float sm[];
    float* sW1 = sm + SW1_OFS;
    float* sW2 = sm + SW2_OFS;
    float* sb1 = sm + SB1_OFS;
    float* sb2 = sm + SB2_OFS;
    int tid = threadIdx.x;

    // W1: (H=128, D=64) row-major -> sW1[d*192 + (j>>3)*12 + (j&7)]
    for (int idx = tid; idx < 128 * 64; idx += 256) {
        int j = idx >> 6, d = idx & 63;
        sW1[d * 192 + (j >> 3) * 12 + (j & 7)] = W1[idx];
    }
    // W2: (D=64, H=128) row-major -> sW2[j*64 + d]
    for (int idx = tid; idx < 64 * 128; idx += 256) {
        int d = idx >> 7, j = idx & 127;
        sW2[j * 64 + d] = W2[idx];
    }
    if (tid < 128)      sb1[(tid >> 3) * 12 + (tid & 7)] = b1[tid];
    else if (tid < 192) sb2[tid - 128] = b2[tid - 128];
    __syncthreads();

    int lane = tid & 31;
    int g = lane & 1;        // row-parity within warp
    int s = lane >> 1;       // slice: z dims [4s,4s+4), h dims [8s,8s+8)
    int warp = tid >> 5;
    float* yb = sm + YB_OFS + warp * 544;    // 8 rows * 68
    float* hb = sm + HB_OFS + warp * 1056;   // 8 rows * 132
    int rbase = blockIdx.x * 64 + warp * 8;

    if (t_off >= 0 && blockIdx.x == 0 && tid < TPTS)
        out[t_off + tid] = (float)tid * (1.0f / 63.0f);

    float sig = expf(z0_log_sigma[0]);
    float z[4][4];
    {
        float4 zm = *(const float4*)(z0_mean + s * 4);
        #pragma unroll
        for (int i = 0; i < 4; i++) {
            int r = rbase + g + 2 * i;
            float4 rv = *(const float4*)(rand_e + (size_t)r * 64 + s * 4);
            z[i][0] = zm.x + sig * rv.x;
            z[i][1] = zm.y + sig * rv.y;
            z[i][2] = zm.z + sig * rv.z;
            z[i][3] = zm.w + sig * rv.w;
        }
    }

    size_t lofs[4];
    #pragma unroll
    for (int i = 0; i < 4; i++)
        lofs[i] = (size_t)(rbase + g + 2 * i) * 64 + s * 4;

    if (z0_off >= 0) {
        #pragma unroll
        for (int i = 0; i < 4; i++)
            *(float4*)(out + z0_off + lofs[i]) =
                make_float4(z[i][0], z[i][1], z[i][2], z[i][3]);
    }
    #pragma unroll
    for (int i = 0; i < 4; i++)   // z at t=0 equals z0
        *(float4*)(out + z_off + lofs[i]) =
            make_float4(z[i][0], z[i][1], z[i][2], z[i][3]);

    const float dt = 1.0f / 63.0f;
    #pragma unroll 1
    for (int step = 0; step < 63; step++) {
        float acc[4][4], y[4][4];
        #pragma unroll
        for (int i = 0; i < 4; i++)
            #pragma unroll
            for (int t = 0; t < 4; t++) {
                y[i][t] = z[i][t];
                acc[i][t] = 0.0f;
            }
        #pragma unroll 1
        for (int st = 0; st < 4; st++) {
            float k[4][4];
            eval4(sW1, sW2, sb1, sb2, yb, hb, g, s, y, k);
            float bw = (st == 1 || st == 2) ? 2.0f : 1.0f;
            float aw = (st == 2) ? dt : ((st == 3) ? 0.0f : 0.5f * dt);
            #pragma unroll
            for (int i = 0; i < 4; i++)
                #pragma unroll
                for (int t = 0; t < 4; t++) {
                    acc[i][t] += bw * k[i][t];
                    y[i][t]   = z[i][t] + aw * k[i][t];
                }
        }
        #pragma unroll
        for (int i = 0; i < 4; i++)
            #pragma unroll
            for (int t = 0; t < 4; t++)
                z[i][t] += (dt * (1.0f / 6.0f)) * acc[i][t];

        size_t tofs = z_off + (size_t)(step + 1) * (NROWS * 64);
        #pragma unroll
        for (int i = 0; i < 4; i++)
            *(float4*)(out + tofs + lofs[i]) =
                make_float4(z[i][0], z[i][1], z[i][2], z[i][3]);
    }
}

extern "C" void kernel_launch(void* const* d_in, const int* in_sizes, int n_in,
                              void* d_out, int out_size)
{
    const float* rand_e       = (const float*)d_in[0];
    const float* z0_mean      = (const float*)d_in[1];
    const float* z0_log_sigma = (const float*)d_in[2];
    const float* W1           = (const float*)d_in[3];
    const float* b1           = (const float*)d_in[4];
    const float* W2           = (const float*)d_in[5];
    const float* b2           = (const float*)d_in[6];

    const long long Z0SZ = (long long)NROWS * 64;   // 524288
    const long long TSZ  = TPTS;                    // 64
    const long long ZSZ  = (long long)TPTS * NROWS * 64;

    long long z0_off, t_off, z_off;
    long long osz = (long long)out_size;
    if (osz == Z0SZ + TSZ + ZSZ)      { z0_off = 0;  t_off = Z0SZ; z_off = Z0SZ + TSZ; }
    else if (osz == ZSZ)              { z0_off = -1; t_off = -1;   z_off = 0; }
    else if (osz == Z0SZ + ZSZ)       { z0_off = 0;  t_off = -1;   z_off = Z0SZ; }
    else                              { z0_off = 0;  t_off = Z0SZ; z_off = Z0SZ + TSZ; }

    cudaFuncSetAttribute(ode_kernel,
                         cudaFuncAttributeMaxDynamicSharedMemorySize,
                         SMEM_FLOATS * sizeof(float));

    ode_kernel<<<NROWS / 64, 256, SMEM_FLOATS * sizeof(float)>>>(
        rand_e, z0_mean, z0_log_sigma, W1, b1, W2, b2,
        (float*)d_out, z0_off, t_off, z_off);
}